// round 1
// baseline (speedup 1.0000x reference)
#include <cuda_runtime.h>
#include <cuda_bf16.h>
#include <math.h>

#define Bsz 2
#define SEQ 2048
#define HIDN 2048
#define NH 16
#define NKV 4
#define HD 128
#define QKVF 5120   // (16*2 + 2*4) * 128

// ---------------- scratch (device globals; no allocs allowed) ----------------
__device__ float g_qkv [Bsz*SEQ*QKVF];     // (b*s, 5120)
__device__ float g_q   [Bsz*NH *SEQ*HD];   // (b, h, s, d)
__device__ float g_k   [Bsz*NKV*SEQ*HD];   // (b, kv, s, d)
__device__ float g_v   [Bsz*NKV*SEQ*HD];   // (b, kv, s, d)
__device__ float g_gate[Bsz*SEQ*NH*HD];    // (b*s, h*d) raw gate (pre-sigmoid)
__device__ float g_attn[Bsz*SEQ*NH*HD];    // (b*s, h*d) gated attention output

// ---------------- generic 128x128 tiled SGEMM, row-major, all dims %128 ----
__global__ __launch_bounds__(256) void sgemm_kernel(
    const float* __restrict__ A, const float* __restrict__ B,
    float* __restrict__ C, int M, int N, int K)
{
    __shared__ float As[8][128];
    __shared__ float Bs[8][128];
    int tid = threadIdx.x;
    int row0 = blockIdx.y * 128, col0 = blockIdx.x * 128;
    int tx = tid & 15, ty = tid >> 4;

    int arow = tid >> 1, acol = (tid & 1) * 4;     // A: 128 rows x 8 k (float4 along K)
    int brow = tid >> 5, bcol = (tid & 31) * 4;    // B: 8 k rows x 128 cols

    const float* Aptr = A + (size_t)(row0 + arow) * K + acol;
    const float* Bptr = B + (size_t)brow * N + col0 + bcol;

    float acc[8][8];
#pragma unroll
    for (int m = 0; m < 8; m++)
#pragma unroll
        for (int n = 0; n < 8; n++) acc[m][n] = 0.f;

    for (int k0 = 0; k0 < K; k0 += 8) {
        float4 a4 = *(const float4*)(Aptr + k0);
        As[acol+0][arow] = a4.x; As[acol+1][arow] = a4.y;
        As[acol+2][arow] = a4.z; As[acol+3][arow] = a4.w;
        *(float4*)&Bs[brow][bcol] = *(const float4*)(Bptr + (size_t)k0 * N);
        __syncthreads();
#pragma unroll
        for (int k = 0; k < 8; k++) {
            float4 a0 = *(float4*)&As[k][ty*8];
            float4 a1 = *(float4*)&As[k][ty*8+4];
            float4 b0 = *(float4*)&Bs[k][tx*8];
            float4 b1 = *(float4*)&Bs[k][tx*8+4];
            float ra[8] = {a0.x,a0.y,a0.z,a0.w,a1.x,a1.y,a1.z,a1.w};
            float rb[8] = {b0.x,b0.y,b0.z,b0.w,b1.x,b1.y,b1.z,b1.w};
#pragma unroll
            for (int m = 0; m < 8; m++)
#pragma unroll
                for (int n = 0; n < 8; n++) acc[m][n] += ra[m] * rb[n];
        }
        __syncthreads();
    }
#pragma unroll
    for (int m = 0; m < 8; m++) {
        float* Crow = C + (size_t)(row0 + ty*8 + m) * N + col0 + tx*8;
        *(float4*)(Crow)     = make_float4(acc[m][0],acc[m][1],acc[m][2],acc[m][3]);
        *(float4*)(Crow + 4) = make_float4(acc[m][4],acc[m][5],acc[m][6],acc[m][7]);
    }
}

// ---------------- RMSNorm + partial RoPE + scatter to q/k/v/gate -------------
__global__ __launch_bounds__(256) void postqkv_kernel(
    const int* __restrict__ positions,
    const float* __restrict__ qw, const float* __restrict__ kw)
{
    int row = blockIdx.x;                 // b*SEQ + s
    int b = row / SEQ, s = row % SEQ;
    int pos = positions[row];
    int lane = threadIdx.x & 31, warp = threadIdx.x >> 5;
    const float* qrow = g_qkv + (size_t)row * QKVF;

    for (int vi = warp; vi < NH + NKV; vi += 8) {
        const float* src; float* dst; const float* w;
        if (vi < NH) {   // q head
            src = qrow + vi * 256;
            dst = g_q + (((size_t)b*NH + vi)*SEQ + s)*HD;
            w = qw;
        } else {         // k head
            int kv = vi - NH;
            src = qrow + NH*2*HD + kv*HD;
            dst = g_k + (((size_t)b*NKV + kv)*SEQ + s)*HD;
            w = kw;
        }
        float x0 = src[lane], x1 = src[lane+32], x2 = src[lane+64], x3 = src[lane+96];
        float ss = x0*x0 + x1*x1 + x2*x2 + x3*x3;
#pragma unroll
        for (int o = 16; o > 0; o >>= 1) ss += __shfl_xor_sync(0xffffffffu, ss, o);
        float inv = rsqrtf(ss * (1.0f/128.0f) + 1e-6f);
        x0 *= inv * (1.f + w[lane]);
        x1 *= inv * (1.f + w[lane+32]);
        x2 *= inv * (1.f + w[lane+64]);
        x3 *= inv * (1.f + w[lane+96]);
        // partial RoPE on dims [0,32): pair (d, d+16), both in x0 across lanes
        int fi = lane & 15;
        float partner = __shfl_xor_sync(0xffffffffu, x0, 16);
        double invf = exp(-(double)fi * (1.0/16.0) * log(5.0e6));
        float ang = (float)pos * (float)invf;   // fp32 product like reference
        double sd, cd;
        sincos((double)ang, &sd, &cd);          // accurate trig regardless of fastmath
        float cf = (float)cd, sf = (float)sd;
        float y0 = (lane < 16) ? (x0*cf - partner*sf) : (x0*cf + partner*sf);
        dst[lane]    = y0;
        dst[lane+32] = x1;
        dst[lane+64] = x2;
        dst[lane+96] = x3;
    }
    // gate (raw) and v copies
    for (int i = threadIdx.x; i < NH*HD; i += blockDim.x) {
        int h = i >> 7, d = i & 127;
        g_gate[(size_t)row*NH*HD + i] = qrow[h*256 + 128 + d];
    }
    for (int i = threadIdx.x; i < NKV*HD; i += blockDim.x) {
        int kv = i >> 7, d = i & 127;
        g_v[(((size_t)b*NKV + kv)*SEQ + s)*HD + d] = qrow[NH*2*HD + NKV*HD + i];
    }
}

// ---------------- causal flash attention (fp32) + fused sigmoid gating -------
#define PITCH 132
__global__ __launch_bounds__(256) void attn_kernel()
{
    extern __shared__ float sm[];
    float* Qs   = sm;                   // 64 x 132
    float* Ks   = sm + 64*PITCH;        // 64 x 132
    float* Vs   = sm + 2*64*PITCH;      // 64 x 132
    float* Ps   = sm + 3*64*PITCH;      // 64 x 66
    float* rowm = Ps + 64*66;
    float* rowl = rowm + 64;
    float* rowc = rowl + 64;

    int tid = threadIdx.x;
    int tx = tid & 15, ty = tid >> 4;
    int hh = blockIdx.y;                 // 0..31
    int b = hh >> 4, h = hh & 15, kv = h >> 2;
    int m_tile = gridDim.x - 1 - blockIdx.x;   // heavy tiles first
    int m0 = m_tile * 64;

    const float* Qg = g_q + (((size_t)b*NH + h)*SEQ + m0)*HD;
    const float* Kg = g_k + ((size_t)b*NKV + kv)*SEQ*HD;
    const float* Vg = g_v + ((size_t)b*NKV + kv)*SEQ*HD;

#pragma unroll
    for (int t = 0; t < 8; t++) {
        int idx = tid + t*256; int i = idx >> 5, d4 = idx & 31;
        *(float4*)&Qs[i*PITCH + d4*4] = *(const float4*)(Qg + i*HD + d4*4);
    }
    if (tid < 64) { rowm[tid] = -3.0e38f; rowl[tid] = 0.f; }

    float o[4][8];
#pragma unroll
    for (int m = 0; m < 4; m++)
#pragma unroll
        for (int c = 0; c < 8; c++) o[m][c] = 0.f;
    __syncthreads();

    int ntiles = m_tile + 1;
    for (int nt = 0; nt < ntiles; nt++) {
        int n0 = nt * 64;
#pragma unroll
        for (int t = 0; t < 8; t++) {
            int idx = tid + t*256; int i = idx >> 5, d4 = idx & 31;
            *(float4*)&Ks[i*PITCH + d4*4] = *(const float4*)(Kg + (size_t)(n0+i)*HD + d4*4);
            *(float4*)&Vs[i*PITCH + d4*4] = *(const float4*)(Vg + (size_t)(n0+i)*HD + d4*4);
        }
        __syncthreads();

        // S = Q K^T (64x64), 4x4 per thread
        float acc[4][4];
#pragma unroll
        for (int m = 0; m < 4; m++)
#pragma unroll
            for (int n = 0; n < 4; n++) acc[m][n] = 0.f;
        for (int d4 = 0; d4 < 32; d4++) {
            float4 qa[4], kb[4];
#pragma unroll
            for (int m = 0; m < 4; m++) qa[m] = *(float4*)&Qs[(ty*4+m)*PITCH + d4*4];
#pragma unroll
            for (int n = 0; n < 4; n++) kb[n] = *(float4*)&Ks[(tx*4+n)*PITCH + d4*4];
#pragma unroll
            for (int m = 0; m < 4; m++)
#pragma unroll
                for (int n = 0; n < 4; n++)
                    acc[m][n] += qa[m].x*kb[n].x + qa[m].y*kb[n].y
                               + qa[m].z*kb[n].z + qa[m].w*kb[n].w;
        }
        const float scale = 0.08838834764831845f;  // 1/sqrt(128)
        bool diag = (n0 == m0);
#pragma unroll
        for (int m = 0; m < 4; m++) {
            int gi = ty*4 + m;
#pragma unroll
            for (int n = 0; n < 4; n++) {
                int gj = tx*4 + n;
                float v = acc[m][n] * scale;
                if (diag && gj > gi) v = -3.0e38f;
                Ps[gi*66 + gj] = v;
            }
        }
        __syncthreads();

        // online softmax (one thread per row)
        if (tid < 64) {
            float mx = -3.0e38f;
#pragma unroll 8
            for (int j = 0; j < 64; j++) mx = fmaxf(mx, Ps[tid*66 + j]);
            float oldm = rowm[tid];
            float newm = fmaxf(oldm, mx);
            float corr = expf(oldm - newm);
            float sum = 0.f;
#pragma unroll 8
            for (int j = 0; j < 64; j++) {
                float p = expf(Ps[tid*66 + j] - newm);
                Ps[tid*66 + j] = p;
                sum += p;
            }
            rowm[tid] = newm;
            rowl[tid] = rowl[tid] * corr + sum;
            rowc[tid] = corr;
        }
        __syncthreads();

        // O = O*corr + P @ V
#pragma unroll
        for (int m = 0; m < 4; m++) {
            float corr = rowc[ty*4 + m];
#pragma unroll
            for (int c = 0; c < 8; c++) o[m][c] *= corr;
        }
        for (int j = 0; j < 64; j++) {
            float pv[4];
#pragma unroll
            for (int m = 0; m < 4; m++) pv[m] = Ps[(ty*4+m)*66 + j];
            float4 v0 = *(float4*)&Vs[j*PITCH + tx*8];
            float4 v1 = *(float4*)&Vs[j*PITCH + tx*8 + 4];
#pragma unroll
            for (int m = 0; m < 4; m++) {
                o[m][0] += pv[m]*v0.x; o[m][1] += pv[m]*v0.y;
                o[m][2] += pv[m]*v0.z; o[m][3] += pv[m]*v0.w;
                o[m][4] += pv[m]*v1.x; o[m][5] += pv[m]*v1.y;
                o[m][6] += pv[m]*v1.z; o[m][7] += pv[m]*v1.w;
            }
        }
        __syncthreads();
    }

    // epilogue: normalize, apply sigmoid gate, write (b*s, h*d)
#pragma unroll
    for (int m = 0; m < 4; m++) {
        int r = ty*4 + m;
        float linv = 1.0f / rowl[r];
        size_t base = ((size_t)b*SEQ + m0 + r)*(NH*HD) + h*HD + tx*8;
#pragma unroll
        for (int c = 0; c < 8; c++) {
            float gv = g_gate[base + c];
            float sg = 1.0f / (1.0f + expf(-gv));
            g_attn[base + c] = o[m][c] * linv * sg;
        }
    }
}

// ---------------- host launch ------------------------------------------------
extern "C" void kernel_launch(void* const* d_in, const int* in_sizes, int n_in,
                              void* d_out, int out_size)
{
    const float* x         = (const float*)d_in[0];
    const int*   positions = (const int*)  d_in[1];
    /* d_in[2] = attention_mask: all-ones, causal mask dominates -> unused */
    const float* wqkv      = (const float*)d_in[3];
    const float* wo        = (const float*)d_in[4];
    const float* qw        = (const float*)d_in[5];
    const float* kw        = (const float*)d_in[6];
    float* out = (float*)d_out;

    float *qkv_p, *attn_p;
    cudaGetSymbolAddress((void**)&qkv_p,  g_qkv);
    cudaGetSymbolAddress((void**)&attn_p, g_attn);

    // 1) QKV projection: (4096 x 2048) @ (2048 x 5120)
    sgemm_kernel<<<dim3(QKVF/128, (Bsz*SEQ)/128), 256>>>(x, wqkv, qkv_p,
                                                         Bsz*SEQ, QKVF, HIDN);
    // 2) norm + rope + scatter
    postqkv_kernel<<<Bsz*SEQ, 256>>>(positions, qw, kw);

    // 3) causal flash attention + gating
    int smem = (3*64*PITCH + 64*66 + 3*64) * (int)sizeof(float);  // 119,040 B
    cudaFuncSetAttribute(attn_kernel, cudaFuncAttributeMaxDynamicSharedMemorySize, smem);
    attn_kernel<<<dim3(SEQ/64, Bsz*NH), 256, smem>>>();

    // 4) output projection: (4096 x 2048) @ (2048 x 2048)
    sgemm_kernel<<<dim3(HIDN/128, (Bsz*SEQ)/128), 256>>>(attn_p, wo, out,
                                                         Bsz*SEQ, HIDN, HIDN);
}

// round 2
// speedup vs baseline: 1.6681x; 1.6681x over previous
#include <cuda_runtime.h>
#include <cuda_bf16.h>
#include <math.h>
#include <stdint.h>

#define Bsz 2
#define SEQ 2048
#define HIDN 2048
#define NH 16
#define NKV 4
#define HD 128
#define QKVF 5120   // (16*2 + 2*4) * 128

// ---------------- scratch (device globals; no allocs allowed) ----------------
__device__ float g_qkv [Bsz*SEQ*QKVF];     // (b*s, 5120)
__device__ float g_q   [Bsz*NH *SEQ*HD];   // (b, h, s, d)
__device__ float g_k   [Bsz*NKV*SEQ*HD];   // (b, kv, s, d)
__device__ float g_v   [Bsz*NKV*SEQ*HD];   // (b, kv, s, d)
__device__ float g_gate[Bsz*SEQ*NH*HD];    // (b*s, h*d) raw gate (pre-sigmoid)
__device__ float g_attn[Bsz*SEQ*NH*HD];    // (b*s, h*d) gated attention output

// ======================= tf32 tensor-core GEMM ==============================
// C(MxN) = A(MxK) @ B(KxN), row-major, M,N,K % 128 == 0.
// 128x128 block tile, KC=32 k-chunk, cp.async double buffer,
// mma.sync.m16n8k8.tf32 (fp32 accumulate).

#define KC 32
#define APITCH 36     // As[m][k] pitch: conflict-free frag loads (4m+k distinct)
#define BPITCH 132    // Bs[k][n] pitch
#define ASTG (128*APITCH)
#define BSTG (KC*BPITCH)

__device__ __forceinline__ void cp_async16(float* sdst, const float* gsrc) {
    uint32_t s = (uint32_t)__cvta_generic_to_shared(sdst);
    asm volatile("cp.async.cg.shared.global [%0], [%1], 16;\n" :: "r"(s), "l"(gsrc));
}
template<int N_> __device__ __forceinline__ void cp_wait() {
    asm volatile("cp.async.wait_group %0;\n" :: "n"(N_) : "memory");
}
__device__ __forceinline__ uint32_t f2tf32(float x) {
    uint32_t r; asm("cvt.rna.tf32.f32 %0, %1;" : "=r"(r) : "f"(x)); return r;
}
__device__ __forceinline__ void mma8(float* c, const uint32_t* a, const uint32_t* b) {
    asm volatile("mma.sync.aligned.m16n8k8.row.col.f32.tf32.tf32.f32 "
        "{%0,%1,%2,%3}, {%4,%5,%6,%7}, {%8,%9}, {%0,%1,%2,%3};\n"
        : "+f"(c[0]), "+f"(c[1]), "+f"(c[2]), "+f"(c[3])
        : "r"(a[0]), "r"(a[1]), "r"(a[2]), "r"(a[3]), "r"(b[0]), "r"(b[1]));
}

__device__ __forceinline__ void gemm_load_stage(
    float* As, float* Bsm, const float* __restrict__ A, const float* __restrict__ B,
    int tid, int row0, int col0, int k0, int N, int K)
{
#pragma unroll
    for (int t = 0; t < 4; t++) {          // A: 128 x 32, float4 along k
        int idx = t*256 + tid;
        int r = idx >> 3, c4 = idx & 7;
        cp_async16(As + r*APITCH + c4*4, A + (size_t)(row0 + r)*K + k0 + c4*4);
    }
#pragma unroll
    for (int t = 0; t < 4; t++) {          // B: 32 x 128, float4 along n
        int idx = t*256 + tid;
        int kr = idx >> 5, n4 = idx & 31;
        cp_async16(Bsm + kr*BPITCH + n4*4, B + (size_t)(k0 + kr)*N + col0 + n4*4);
    }
    asm volatile("cp.async.commit_group;\n");
}

__global__ __launch_bounds__(256, 2) void tf32gemm_kernel(
    const float* __restrict__ A, const float* __restrict__ B,
    float* __restrict__ C, int M, int N, int K)
{
    extern __shared__ float smem[];
    float* As  = smem;              // 2 stages of 128x36
    float* Bsm = smem + 2*ASTG;     // 2 stages of 32x132

    const int tid = threadIdx.x;
    const int row0 = blockIdx.y * 128, col0 = blockIdx.x * 128;
    const int warp = tid >> 5, lane = tid & 31;
    const int wm = warp >> 1, wn = warp & 1;   // 4 x 2 warps; warp tile 32m x 64n
    const int g = lane >> 2, q = lane & 3;

    float c[2][8][4];
#pragma unroll
    for (int mt = 0; mt < 2; mt++)
#pragma unroll
        for (int nt = 0; nt < 8; nt++)
#pragma unroll
            for (int i = 0; i < 4; i++) c[mt][nt][i] = 0.f;

    const int T = K / KC;
    gemm_load_stage(As, Bsm, A, B, tid, row0, col0, 0, N, K);

    for (int it = 0; it < T; it++) {
        if (it + 1 < T) {
            gemm_load_stage(As + ((it+1)&1)*ASTG, Bsm + ((it+1)&1)*BSTG,
                            A, B, tid, row0, col0, (it+1)*KC, N, K);
            cp_wait<1>();
        } else {
            cp_wait<0>();
        }
        __syncthreads();

        const float* As_ = As  + (it&1)*ASTG;
        const float* Bs_ = Bsm + (it&1)*BSTG;
#pragma unroll
        for (int kk = 0; kk < KC; kk += 8) {
            uint32_t af[2][4], bf[8][2];
#pragma unroll
            for (int mt = 0; mt < 2; mt++) {
                const float* p = As_ + (wm*32 + mt*16 + g)*APITCH + kk + q;
                af[mt][0] = f2tf32(p[0]);
                af[mt][2] = f2tf32(p[4]);
                af[mt][1] = f2tf32(p[8*APITCH]);
                af[mt][3] = f2tf32(p[8*APITCH + 4]);
            }
#pragma unroll
            for (int nt = 0; nt < 8; nt++) {
                int cc = wn*64 + nt*8 + g;
                bf[nt][0] = f2tf32(Bs_[(kk + q)*BPITCH + cc]);
                bf[nt][1] = f2tf32(Bs_[(kk + q + 4)*BPITCH + cc]);
            }
#pragma unroll
            for (int mt = 0; mt < 2; mt++)
#pragma unroll
                for (int nt = 0; nt < 8; nt++)
                    mma8(c[mt][nt], af[mt], bf[nt]);
        }
        __syncthreads();
    }

    // epilogue
#pragma unroll
    for (int mt = 0; mt < 2; mt++) {
        int r_ = row0 + wm*32 + mt*16 + g;
#pragma unroll
        for (int nt = 0; nt < 8; nt++) {
            int cc = col0 + wn*64 + nt*8 + q*2;
            *(float2*)(C + (size_t)r_*N + cc)     = make_float2(c[mt][nt][0], c[mt][nt][1]);
            *(float2*)(C + (size_t)(r_+8)*N + cc) = make_float2(c[mt][nt][2], c[mt][nt][3]);
        }
    }
}

// ---------------- RMSNorm + partial RoPE + scatter to q/k/v/gate -------------
__global__ __launch_bounds__(256) void postqkv_kernel(
    const int* __restrict__ positions,
    const float* __restrict__ qw, const float* __restrict__ kw)
{
    int row = blockIdx.x;                 // b*SEQ + s
    int b = row / SEQ, s = row % SEQ;
    int pos = positions[row];
    int lane = threadIdx.x & 31, warp = threadIdx.x >> 5;
    const float* qrow = g_qkv + (size_t)row * QKVF;

    for (int vi = warp; vi < NH + NKV; vi += 8) {
        const float* src; float* dst; const float* w;
        if (vi < NH) {   // q head
            src = qrow + vi * 256;
            dst = g_q + (((size_t)b*NH + vi)*SEQ + s)*HD;
            w = qw;
        } else {         // k head
            int kv = vi - NH;
            src = qrow + NH*2*HD + kv*HD;
            dst = g_k + (((size_t)b*NKV + kv)*SEQ + s)*HD;
            w = kw;
        }
        float x0 = src[lane], x1 = src[lane+32], x2 = src[lane+64], x3 = src[lane+96];
        float ss = x0*x0 + x1*x1 + x2*x2 + x3*x3;
#pragma unroll
        for (int o = 16; o > 0; o >>= 1) ss += __shfl_xor_sync(0xffffffffu, ss, o);
        float inv = rsqrtf(ss * (1.0f/128.0f) + 1e-6f);
        x0 *= inv * (1.f + w[lane]);
        x1 *= inv * (1.f + w[lane+32]);
        x2 *= inv * (1.f + w[lane+64]);
        x3 *= inv * (1.f + w[lane+96]);
        // partial RoPE on dims [0,32): pair (d, d+16), both in x0 across lanes
        int fi = lane & 15;
        float partner = __shfl_xor_sync(0xffffffffu, x0, 16);
        double invf = exp(-(double)fi * (1.0/16.0) * log(5.0e6));
        float ang = (float)pos * (float)invf;   // fp32 product like reference
        double sd, cd;
        sincos((double)ang, &sd, &cd);
        float cf = (float)cd, sf = (float)sd;
        float y0 = (lane < 16) ? (x0*cf - partner*sf) : (x0*cf + partner*sf);
        dst[lane]    = y0;
        dst[lane+32] = x1;
        dst[lane+64] = x2;
        dst[lane+96] = x3;
    }
    // gate (raw) and v copies
    for (int i = threadIdx.x; i < NH*HD; i += blockDim.x) {
        int h = i >> 7, d = i & 127;
        g_gate[(size_t)row*NH*HD + i] = qrow[h*256 + 128 + d];
    }
    for (int i = threadIdx.x; i < NKV*HD; i += blockDim.x) {
        int kv = i >> 7, d = i & 127;
        g_v[(((size_t)b*NKV + kv)*SEQ + s)*HD + d] = qrow[NH*2*HD + NKV*HD + i];
    }
}

// ---------------- causal flash attention (fp32) + fused sigmoid gating -------
#define PITCH 132
__global__ __launch_bounds__(256) void attn_kernel()
{
    extern __shared__ float sm[];
    float* Qs   = sm;                   // 64 x 132
    float* Ks   = sm + 64*PITCH;        // 64 x 132
    float* Vs   = sm + 2*64*PITCH;      // 64 x 132
    float* Ps   = sm + 3*64*PITCH;      // 64 x 66
    float* rowm = Ps + 64*66;
    float* rowl = rowm + 64;
    float* rowc = rowl + 64;

    int tid = threadIdx.x;
    int tx = tid & 15, ty = tid >> 4;
    int hh = blockIdx.y;                 // 0..31
    int b = hh >> 4, h = hh & 15, kv = h >> 2;
    int m_tile = gridDim.x - 1 - blockIdx.x;   // heavy tiles first
    int m0 = m_tile * 64;

    const float* Qg = g_q + (((size_t)b*NH + h)*SEQ + m0)*HD;
    const float* Kg = g_k + ((size_t)b*NKV + kv)*SEQ*HD;
    const float* Vg = g_v + ((size_t)b*NKV + kv)*SEQ*HD;

#pragma unroll
    for (int t = 0; t < 8; t++) {
        int idx = tid + t*256; int i = idx >> 5, d4 = idx & 31;
        *(float4*)&Qs[i*PITCH + d4*4] = *(const float4*)(Qg + i*HD + d4*4);
    }
    if (tid < 64) { rowm[tid] = -3.0e38f; rowl[tid] = 0.f; }

    float o[4][8];
#pragma unroll
    for (int m = 0; m < 4; m++)
#pragma unroll
        for (int c = 0; c < 8; c++) o[m][c] = 0.f;
    __syncthreads();

    int ntiles = m_tile + 1;
    for (int nt = 0; nt < ntiles; nt++) {
        int n0 = nt * 64;
#pragma unroll
        for (int t = 0; t < 8; t++) {
            int idx = tid + t*256; int i = idx >> 5, d4 = idx & 31;
            *(float4*)&Ks[i*PITCH + d4*4] = *(const float4*)(Kg + (size_t)(n0+i)*HD + d4*4);
            *(float4*)&Vs[i*PITCH + d4*4] = *(const float4*)(Vg + (size_t)(n0+i)*HD + d4*4);
        }
        __syncthreads();

        // S = Q K^T (64x64), 4x4 per thread
        float acc[4][4];
#pragma unroll
        for (int m = 0; m < 4; m++)
#pragma unroll
            for (int n = 0; n < 4; n++) acc[m][n] = 0.f;
        for (int d4 = 0; d4 < 32; d4++) {
            float4 qa[4], kb[4];
#pragma unroll
            for (int m = 0; m < 4; m++) qa[m] = *(float4*)&Qs[(ty*4+m)*PITCH + d4*4];
#pragma unroll
            for (int n = 0; n < 4; n++) kb[n] = *(float4*)&Ks[(tx*4+n)*PITCH + d4*4];
#pragma unroll
            for (int m = 0; m < 4; m++)
#pragma unroll
                for (int n = 0; n < 4; n++)
                    acc[m][n] += qa[m].x*kb[n].x + qa[m].y*kb[n].y
                               + qa[m].z*kb[n].z + qa[m].w*kb[n].w;
        }
        const float scale = 0.08838834764831845f;  // 1/sqrt(128)
        bool diag = (n0 == m0);
#pragma unroll
        for (int m = 0; m < 4; m++) {
            int gi = ty*4 + m;
#pragma unroll
            for (int n = 0; n < 4; n++) {
                int gj = tx*4 + n;
                float v = acc[m][n] * scale;
                if (diag && gj > gi) v = -3.0e38f;
                Ps[gi*66 + gj] = v;
            }
        }
        __syncthreads();

        // online softmax: 4 threads per row, 16 cols each
        {
            int r = tid >> 2, sub = tid & 3;
            float* Prow = Ps + r*66 + sub*16;
            float mx = -3.0e38f;
#pragma unroll
            for (int j = 0; j < 16; j++) mx = fmaxf(mx, Prow[j]);
            mx = fmaxf(mx, __shfl_xor_sync(0xffffffffu, mx, 1));
            mx = fmaxf(mx, __shfl_xor_sync(0xffffffffu, mx, 2));
            float oldm = rowm[r];
            float newm = fmaxf(oldm, mx);
            float sum = 0.f;
#pragma unroll
            for (int j = 0; j < 16; j++) {
                float p = expf(Prow[j] - newm);
                Prow[j] = p;
                sum += p;
            }
            sum += __shfl_xor_sync(0xffffffffu, sum, 1);
            sum += __shfl_xor_sync(0xffffffffu, sum, 2);
            if (sub == 0) {
                float corr = expf(oldm - newm);
                rowm[r] = newm;
                rowl[r] = rowl[r] * corr + sum;
                rowc[r] = corr;
            }
        }
        __syncthreads();

        // O = O*corr + P @ V
#pragma unroll
        for (int m = 0; m < 4; m++) {
            float corr = rowc[ty*4 + m];
#pragma unroll
            for (int c = 0; c < 8; c++) o[m][c] *= corr;
        }
        for (int j = 0; j < 64; j++) {
            float pv[4];
#pragma unroll
            for (int m = 0; m < 4; m++) pv[m] = Ps[(ty*4+m)*66 + j];
            float4 v0 = *(float4*)&Vs[j*PITCH + tx*8];
            float4 v1 = *(float4*)&Vs[j*PITCH + tx*8 + 4];
#pragma unroll
            for (int m = 0; m < 4; m++) {
                o[m][0] += pv[m]*v0.x; o[m][1] += pv[m]*v0.y;
                o[m][2] += pv[m]*v0.z; o[m][3] += pv[m]*v0.w;
                o[m][4] += pv[m]*v1.x; o[m][5] += pv[m]*v1.y;
                o[m][6] += pv[m]*v1.z; o[m][7] += pv[m]*v1.w;
            }
        }
        __syncthreads();
    }

    // epilogue: normalize, apply sigmoid gate, write (b*s, h*d)
#pragma unroll
    for (int m = 0; m < 4; m++) {
        int r = ty*4 + m;
        float linv = 1.0f / rowl[r];
        size_t base = ((size_t)b*SEQ + m0 + r)*(NH*HD) + h*HD + tx*8;
#pragma unroll
        for (int c = 0; c < 8; c++) {
            float gv = g_gate[base + c];
            float sg = 1.0f / (1.0f + expf(-gv));
            g_attn[base + c] = o[m][c] * linv * sg;
        }
    }
}

// ---------------- host launch ------------------------------------------------
extern "C" void kernel_launch(void* const* d_in, const int* in_sizes, int n_in,
                              void* d_out, int out_size)
{
    const float* x         = (const float*)d_in[0];
    const int*   positions = (const int*)  d_in[1];
    /* d_in[2] = attention_mask: all-ones, causal mask dominates -> unused */
    const float* wqkv      = (const float*)d_in[3];
    const float* wo        = (const float*)d_in[4];
    const float* qw        = (const float*)d_in[5];
    const float* kw        = (const float*)d_in[6];
    float* out = (float*)d_out;

    float *qkv_p, *attn_p;
    cudaGetSymbolAddress((void**)&qkv_p,  g_qkv);
    cudaGetSymbolAddress((void**)&attn_p, g_attn);

    int gsmem = (2*ASTG + 2*BSTG) * (int)sizeof(float);   // 70,656 B
    cudaFuncSetAttribute(tf32gemm_kernel, cudaFuncAttributeMaxDynamicSharedMemorySize, gsmem);

    // 1) QKV projection: (4096 x 2048) @ (2048 x 5120)
    tf32gemm_kernel<<<dim3(QKVF/128, (Bsz*SEQ)/128), 256, gsmem>>>(
        x, wqkv, qkv_p, Bsz*SEQ, QKVF, HIDN);

    // 2) norm + rope + scatter
    postqkv_kernel<<<Bsz*SEQ, 256>>>(positions, qw, kw);

    // 3) causal flash attention + gating
    int smem = (3*64*PITCH + 64*66 + 3*64) * (int)sizeof(float);  // 119,040 B
    cudaFuncSetAttribute(attn_kernel, cudaFuncAttributeMaxDynamicSharedMemorySize, smem);
    attn_kernel<<<dim3(SEQ/64, Bsz*NH), 256, smem>>>();

    // 4) output projection: (4096 x 2048) @ (2048 x 2048)
    tf32gemm_kernel<<<dim3(HIDN/128, (Bsz*SEQ)/128), 256, gsmem>>>(
        attn_p, wo, out, Bsz*SEQ, HIDN, HIDN);
}

// round 3
// speedup vs baseline: 3.9870x; 2.3902x over previous
#include <cuda_runtime.h>
#include <cuda_bf16.h>
#include <math.h>
#include <stdint.h>

#define Bsz 2
#define SEQ 2048
#define HIDN 2048
#define NH 16
#define NKV 4
#define HD 128
#define QKVF 5120   // (16*2 + 2*4) * 128

// ---------------- scratch (device globals; no allocs allowed) ----------------
__device__ float g_qkv [Bsz*SEQ*QKVF];     // (b*s, 5120)
__device__ float g_q   [Bsz*NH *SEQ*HD];   // (b, h, s, d)
__device__ float g_k   [Bsz*NKV*SEQ*HD];   // (b, kv, s, d)
__device__ float g_v   [Bsz*NKV*SEQ*HD];   // (b, kv, s, d)
__device__ float g_gate[Bsz*SEQ*NH*HD];    // (b*s, h*d) raw gate (pre-sigmoid)
__device__ float g_attn[Bsz*SEQ*NH*HD];    // (b*s, h*d) gated attention output
__device__ float g_rcos[Bsz*SEQ*16];       // rope tables per (row, freq)
__device__ float g_rsin[Bsz*SEQ*16];

// ======================= tf32 helpers =======================================
__device__ __forceinline__ void cp_async16(float* sdst, const float* gsrc) {
    uint32_t s = (uint32_t)__cvta_generic_to_shared(sdst);
    asm volatile("cp.async.cg.shared.global [%0], [%1], 16;\n" :: "r"(s), "l"(gsrc));
}
template<int N_> __device__ __forceinline__ void cp_wait() {
    asm volatile("cp.async.wait_group %0;\n" :: "n"(N_) : "memory");
}
__device__ __forceinline__ uint32_t f2tf32(float x) {
    uint32_t r; asm("cvt.rna.tf32.f32 %0, %1;" : "=r"(r) : "f"(x)); return r;
}
__device__ __forceinline__ void mma8(float* c, const uint32_t* a, const uint32_t* b) {
    asm volatile("mma.sync.aligned.m16n8k8.row.col.f32.tf32.tf32.f32 "
        "{%0,%1,%2,%3}, {%4,%5,%6,%7}, {%8,%9}, {%0,%1,%2,%3};\n"
        : "+f"(c[0]), "+f"(c[1]), "+f"(c[2]), "+f"(c[3])
        : "r"(a[0]), "r"(a[1]), "r"(a[2]), "r"(a[3]), "r"(b[0]), "r"(b[1]));
}

// ======================= tf32 tensor-core GEMM ==============================
#define KC 32
#define APITCH 36
#define BPITCH 132
#define ASTG (128*APITCH)
#define BSTG (KC*BPITCH)

__device__ __forceinline__ void gemm_load_stage(
    float* As, float* Bsm, const float* __restrict__ A, const float* __restrict__ B,
    int tid, int row0, int col0, int k0, int N, int K)
{
#pragma unroll
    for (int t = 0; t < 4; t++) {
        int idx = t*256 + tid;
        int r = idx >> 3, c4 = idx & 7;
        cp_async16(As + r*APITCH + c4*4, A + (size_t)(row0 + r)*K + k0 + c4*4);
    }
#pragma unroll
    for (int t = 0; t < 4; t++) {
        int idx = t*256 + tid;
        int kr = idx >> 5, n4 = idx & 31;
        cp_async16(Bsm + kr*BPITCH + n4*4, B + (size_t)(k0 + kr)*N + col0 + n4*4);
    }
    asm volatile("cp.async.commit_group;\n");
}

__global__ __launch_bounds__(256, 2) void tf32gemm_kernel(
    const float* __restrict__ A, const float* __restrict__ B,
    float* __restrict__ C, int M, int N, int K)
{
    extern __shared__ float smem[];
    float* As  = smem;
    float* Bsm = smem + 2*ASTG;

    const int tid = threadIdx.x;
    const int row0 = blockIdx.y * 128, col0 = blockIdx.x * 128;
    const int warp = tid >> 5, lane = tid & 31;
    const int wm = warp >> 1, wn = warp & 1;
    const int g = lane >> 2, q = lane & 3;

    float c[2][8][4];
#pragma unroll
    for (int mt = 0; mt < 2; mt++)
#pragma unroll
        for (int nt = 0; nt < 8; nt++)
#pragma unroll
            for (int i = 0; i < 4; i++) c[mt][nt][i] = 0.f;

    const int T = K / KC;
    gemm_load_stage(As, Bsm, A, B, tid, row0, col0, 0, N, K);

    for (int it = 0; it < T; it++) {
        if (it + 1 < T) {
            gemm_load_stage(As + ((it+1)&1)*ASTG, Bsm + ((it+1)&1)*BSTG,
                            A, B, tid, row0, col0, (it+1)*KC, N, K);
            cp_wait<1>();
        } else {
            cp_wait<0>();
        }
        __syncthreads();

        const float* As_ = As  + (it&1)*ASTG;
        const float* Bs_ = Bsm + (it&1)*BSTG;
#pragma unroll
        for (int kk = 0; kk < KC; kk += 8) {
            uint32_t af[2][4], bf[8][2];
#pragma unroll
            for (int mt = 0; mt < 2; mt++) {
                const float* p = As_ + (wm*32 + mt*16 + g)*APITCH + kk + q;
                af[mt][0] = f2tf32(p[0]);
                af[mt][2] = f2tf32(p[4]);
                af[mt][1] = f2tf32(p[8*APITCH]);
                af[mt][3] = f2tf32(p[8*APITCH + 4]);
            }
#pragma unroll
            for (int nt = 0; nt < 8; nt++) {
                int cc = wn*64 + nt*8 + g;
                bf[nt][0] = f2tf32(Bs_[(kk + q)*BPITCH + cc]);
                bf[nt][1] = f2tf32(Bs_[(kk + q + 4)*BPITCH + cc]);
            }
#pragma unroll
            for (int mt = 0; mt < 2; mt++)
#pragma unroll
                for (int nt = 0; nt < 8; nt++)
                    mma8(c[mt][nt], af[mt], bf[nt]);
        }
        __syncthreads();
    }

#pragma unroll
    for (int mt = 0; mt < 2; mt++) {
        int r_ = row0 + wm*32 + mt*16 + g;
#pragma unroll
        for (int nt = 0; nt < 8; nt++) {
            int cc = col0 + wn*64 + nt*8 + q*2;
            *(float2*)(C + (size_t)r_*N + cc)     = make_float2(c[mt][nt][0], c[mt][nt][1]);
            *(float2*)(C + (size_t)(r_+8)*N + cc) = make_float2(c[mt][nt][2], c[mt][nt][3]);
        }
    }
}

// ---------------- rope table (fp64 trig once per (row,freq)) -----------------
__global__ __launch_bounds__(256) void rope_table_kernel(const int* __restrict__ positions)
{
    int i = blockIdx.x * 256 + threadIdx.x;   // < 4096*16
    int row = i >> 4, fi = i & 15;
    int pos = positions[row];
    double invf = exp(-(double)fi * (1.0/16.0) * log(5.0e6));
    float ang = (float)pos * (float)invf;
    double sd, cd;
    sincos((double)ang, &sd, &cd);
    g_rcos[i] = (float)cd;
    g_rsin[i] = (float)sd;
}

// ---------------- RMSNorm + partial RoPE + scatter to q/k/v/gate -------------
__global__ __launch_bounds__(256) void postqkv_kernel(
    const float* __restrict__ qw, const float* __restrict__ kw)
{
    int row = blockIdx.x;                 // b*SEQ + s
    int b = row / SEQ, s = row % SEQ;
    int lane = threadIdx.x & 31, warp = threadIdx.x >> 5;
    const float* qrow = g_qkv + (size_t)row * QKVF;

    for (int vi = warp; vi < NH + NKV; vi += 8) {
        const float* src; float* dst; const float* w;
        if (vi < NH) {
            src = qrow + vi * 256;
            dst = g_q + (((size_t)b*NH + vi)*SEQ + s)*HD;
            w = qw;
        } else {
            int kv = vi - NH;
            src = qrow + NH*2*HD + kv*HD;
            dst = g_k + (((size_t)b*NKV + kv)*SEQ + s)*HD;
            w = kw;
        }
        float x0 = src[lane], x1 = src[lane+32], x2 = src[lane+64], x3 = src[lane+96];
        float ss = x0*x0 + x1*x1 + x2*x2 + x3*x3;
#pragma unroll
        for (int o = 16; o > 0; o >>= 1) ss += __shfl_xor_sync(0xffffffffu, ss, o);
        float inv = rsqrtf(ss * (1.0f/128.0f) + 1e-6f);
        x0 *= inv * (1.f + w[lane]);
        x1 *= inv * (1.f + w[lane+32]);
        x2 *= inv * (1.f + w[lane+64]);
        x3 *= inv * (1.f + w[lane+96]);
        int fi = lane & 15;
        float partner = __shfl_xor_sync(0xffffffffu, x0, 16);
        float cf = g_rcos[row*16 + fi], sf = g_rsin[row*16 + fi];
        float y0 = (lane < 16) ? (x0*cf - partner*sf) : (x0*cf + partner*sf);
        dst[lane]    = y0;
        dst[lane+32] = x1;
        dst[lane+64] = x2;
        dst[lane+96] = x3;
    }
    for (int i = threadIdx.x; i < NH*HD; i += blockDim.x) {
        int h = i >> 7, d = i & 127;
        g_gate[(size_t)row*NH*HD + i] = qrow[h*256 + 128 + d];
    }
    for (int i = threadIdx.x; i < NKV*HD; i += blockDim.x) {
        int kv = i >> 7, d = i & 127;
        g_v[(((size_t)b*NKV + kv)*SEQ + s)*HD + d] = qrow[NH*2*HD + NKV*HD + i];
    }
}

// ---------------- tensor-core causal flash attention + gating ----------------
// BM=64 q-rows per CTA, 4 warps x m16.  tf32 mma for QK^T and P@V.
#define KPITCH 132
#define VPITCH 68
#define PPITCH 68
#define AT_SMEM_WORDS (64*KPITCH + 128*VPITCH + 64*PPITCH)

__global__ __launch_bounds__(128, 2) void attn_mma_kernel()
{
    extern __shared__ uint32_t smu[];
    uint32_t* Ks = smu;                   // 64 x 132 (n-major, tf32 bits)
    uint32_t* Vt = smu + 64*KPITCH;       // 128 x 68 (d-major, tf32 bits)
    uint32_t* Ps = Vt + 128*VPITCH;       // 64 x 68  (tf32 bits)

    const int tid = threadIdx.x, lane = tid & 31, warp = tid >> 5;
    const int g = lane >> 2, q = lane & 3;
    const int hh = blockIdx.y;
    const int b = hh >> 4, h = hh & 15, kvh = h >> 2;
    const int m_tile = gridDim.x - 1 - blockIdx.x;   // heavy tiles first
    const int m0 = m_tile * 64;

    const float* Qg = g_q + (((size_t)b*NH + h)*SEQ + m0)*HD;
    const float* Kg = g_k + ((size_t)b*NKV + kvh)*SEQ*HD;
    const float* Vg = g_v + ((size_t)b*NKV + kvh)*SEQ*HD;

    // Q fragments in registers, pre-scaled by 1/sqrt(D)
    const float scale = 0.08838834764831845f;
    uint32_t aq[16][4];
    {
        const float* q0 = Qg + (size_t)(warp*16 + g)*HD;
        const float* q1 = q0 + 8*HD;
#pragma unroll
        for (int ks = 0; ks < 16; ks++) {
            aq[ks][0] = f2tf32(q0[ks*8 + q]     * scale);
            aq[ks][1] = f2tf32(q1[ks*8 + q]     * scale);
            aq[ks][2] = f2tf32(q0[ks*8 + q + 4] * scale);
            aq[ks][3] = f2tf32(q1[ks*8 + q + 4] * scale);
        }
    }

    float o[16][4];
#pragma unroll
    for (int nt = 0; nt < 16; nt++)
#pragma unroll
        for (int i = 0; i < 4; i++) o[nt][i] = 0.f;
    float rm0 = -3.0e38f, rm1 = -3.0e38f, rl0 = 0.f, rl1 = 0.f;

    for (int ktile = 0; ktile <= m_tile; ktile++) {
        const int n0 = ktile * 64;
        __syncthreads();   // previous tile's mma reads done before overwrite

        // K tile: 64 x 128, cvt on store, conflict-free uint4 STS
#pragma unroll
        for (int t = 0; t < 16; t++) {
            int idx = t*128 + tid;
            int r = idx >> 5, c4 = idx & 31;
            float4 k4 = *(const float4*)(Kg + (size_t)(n0 + r)*HD + c4*4);
            uint4 kt4 = make_uint4(f2tf32(k4.x), f2tf32(k4.y), f2tf32(k4.z), f2tf32(k4.w));
            *(uint4*)(Ks + r*KPITCH + c4*4) = kt4;
        }
        // V tile transposed to d-major: thread tid owns column d=tid
#pragma unroll 16
        for (int t = 0; t < 64; t++) {
            float v = Vg[(size_t)(n0 + t)*HD + tid];
            Vt[tid*VPITCH + t] = f2tf32(v);
        }
        __syncthreads();

        // S = Q K^T  (64x64 per CTA, warp: rows warp*16..+15)
        float sc[8][4];
#pragma unroll
        for (int nt = 0; nt < 8; nt++)
#pragma unroll
            for (int i = 0; i < 4; i++) sc[nt][i] = 0.f;
#pragma unroll
        for (int kk = 0; kk < 16; kk++) {
            uint32_t bf[8][2];
#pragma unroll
            for (int nt = 0; nt < 8; nt++) {
                const uint32_t* kp = Ks + (nt*8 + g)*KPITCH + kk*8 + q;
                bf[nt][0] = kp[0];
                bf[nt][1] = kp[4];
            }
#pragma unroll
            for (int nt = 0; nt < 8; nt++)
                mma8(sc[nt], aq[kk], bf[nt]);
        }

        // causal mask on diagonal tile
        if (ktile == m_tile) {
            int r0 = warp*16 + g;
#pragma unroll
            for (int nt = 0; nt < 8; nt++) {
                int c0 = nt*8 + 2*q;
                if (c0     > r0)     sc[nt][0] = -3.0e38f;
                if (c0 + 1 > r0)     sc[nt][1] = -3.0e38f;
                if (c0     > r0 + 8) sc[nt][2] = -3.0e38f;
                if (c0 + 1 > r0 + 8) sc[nt][3] = -3.0e38f;
            }
        }

        // online softmax (rows g and g+8 of this warp's m16 tile)
        float mx0 = -3.0e38f, mx1 = -3.0e38f;
#pragma unroll
        for (int nt = 0; nt < 8; nt++) {
            mx0 = fmaxf(mx0, fmaxf(sc[nt][0], sc[nt][1]));
            mx1 = fmaxf(mx1, fmaxf(sc[nt][2], sc[nt][3]));
        }
        mx0 = fmaxf(mx0, __shfl_xor_sync(0xffffffffu, mx0, 1));
        mx0 = fmaxf(mx0, __shfl_xor_sync(0xffffffffu, mx0, 2));
        mx1 = fmaxf(mx1, __shfl_xor_sync(0xffffffffu, mx1, 1));
        mx1 = fmaxf(mx1, __shfl_xor_sync(0xffffffffu, mx1, 2));
        float nm0 = fmaxf(rm0, mx0), nm1 = fmaxf(rm1, mx1);
        float corr0 = __expf(rm0 - nm0), corr1 = __expf(rm1 - nm1);
        float sum0 = 0.f, sum1 = 0.f;
#pragma unroll
        for (int nt = 0; nt < 8; nt++) {
            sc[nt][0] = __expf(sc[nt][0] - nm0); sum0 += sc[nt][0];
            sc[nt][1] = __expf(sc[nt][1] - nm0); sum0 += sc[nt][1];
            sc[nt][2] = __expf(sc[nt][2] - nm1); sum1 += sc[nt][2];
            sc[nt][3] = __expf(sc[nt][3] - nm1); sum1 += sc[nt][3];
        }
        sum0 += __shfl_xor_sync(0xffffffffu, sum0, 1);
        sum0 += __shfl_xor_sync(0xffffffffu, sum0, 2);
        sum1 += __shfl_xor_sync(0xffffffffu, sum1, 1);
        sum1 += __shfl_xor_sync(0xffffffffu, sum1, 2);
        rl0 = rl0 * corr0 + sum0;  rl1 = rl1 * corr1 + sum1;
        rm0 = nm0;  rm1 = nm1;

        // store P (tf32 bits) to warp-private Ps rows
        {
            uint32_t* p0 = Ps + (warp*16 + g)*PPITCH;
            uint32_t* p1 = p0 + 8*PPITCH;
#pragma unroll
            for (int nt = 0; nt < 8; nt++) {
                int cc = nt*8 + 2*q;
                p0[cc]   = f2tf32(sc[nt][0]);  p0[cc+1] = f2tf32(sc[nt][1]);
                p1[cc]   = f2tf32(sc[nt][2]);  p1[cc+1] = f2tf32(sc[nt][3]);
            }
        }
        __syncwarp();

        // rescale O, then O += P @ V
#pragma unroll
        for (int nt = 0; nt < 16; nt++) {
            o[nt][0] *= corr0; o[nt][1] *= corr0;
            o[nt][2] *= corr1; o[nt][3] *= corr1;
        }
#pragma unroll
        for (int kk = 0; kk < 8; kk++) {
            uint32_t ap[4];
            const uint32_t* pp = Ps + (warp*16 + g)*PPITCH + kk*8 + q;
            ap[0] = pp[0];
            ap[2] = pp[4];
            ap[1] = pp[8*PPITCH];
            ap[3] = pp[8*PPITCH + 4];
#pragma unroll
            for (int nt = 0; nt < 16; nt++) {
                const uint32_t* vp = Vt + (nt*8 + g)*VPITCH + kk*8 + q;
                uint32_t bv[2] = { vp[0], vp[4] };
                mma8(o[nt], ap, bv);
            }
        }
    }

    // epilogue: normalize, sigmoid-gate, write to (b*s, h*d)
    float linv0 = 1.0f / rl0, linv1 = 1.0f / rl1;
    int r0 = m0 + warp*16 + g;
#pragma unroll
    for (int nt = 0; nt < 16; nt++) {
        int d = nt*8 + 2*q;
        size_t base0 = ((size_t)b*SEQ + r0)*(NH*HD) + h*HD + d;
        size_t base1 = base0 + 8*(size_t)(NH*HD);
        float g00 = g_gate[base0], g01 = g_gate[base0+1];
        float g10 = g_gate[base1], g11 = g_gate[base1+1];
        float2 o0 = make_float2(o[nt][0]*linv0 / (1.f + __expf(-g00)),
                                o[nt][1]*linv0 / (1.f + __expf(-g01)));
        float2 o1 = make_float2(o[nt][2]*linv1 / (1.f + __expf(-g10)),
                                o[nt][3]*linv1 / (1.f + __expf(-g11)));
        *(float2*)(g_attn + base0) = o0;
        *(float2*)(g_attn + base1) = o1;
    }
}

// ---------------- host launch ------------------------------------------------
extern "C" void kernel_launch(void* const* d_in, const int* in_sizes, int n_in,
                              void* d_out, int out_size)
{
    const float* x         = (const float*)d_in[0];
    const int*   positions = (const int*)  d_in[1];
    /* d_in[2] = attention_mask: all-ones; causal mask dominates -> unused */
    const float* wqkv      = (const float*)d_in[3];
    const float* wo        = (const float*)d_in[4];
    const float* qw        = (const float*)d_in[5];
    const float* kw        = (const float*)d_in[6];
    float* out = (float*)d_out;

    float *qkv_p, *attn_p;
    cudaGetSymbolAddress((void**)&qkv_p,  g_qkv);
    cudaGetSymbolAddress((void**)&attn_p, g_attn);

    int gsmem = (2*ASTG + 2*BSTG) * (int)sizeof(float);
    cudaFuncSetAttribute(tf32gemm_kernel, cudaFuncAttributeMaxDynamicSharedMemorySize, gsmem);

    // 1) QKV projection
    tf32gemm_kernel<<<dim3(QKVF/128, (Bsz*SEQ)/128), 256, gsmem>>>(
        x, wqkv, qkv_p, Bsz*SEQ, QKVF, HIDN);

    // 2) rope table + norm/rope/scatter
    rope_table_kernel<<<(Bsz*SEQ*16)/256, 256>>>(positions);
    postqkv_kernel<<<Bsz*SEQ, 256>>>(qw, kw);

    // 3) tensor-core causal flash attention + gating
    int asmem = AT_SMEM_WORDS * (int)sizeof(uint32_t);   // 86,016 B
    cudaFuncSetAttribute(attn_mma_kernel, cudaFuncAttributeMaxDynamicSharedMemorySize, asmem);
    attn_mma_kernel<<<dim3(SEQ/64, Bsz*NH), 128, asmem>>>();

    // 4) output projection
    tf32gemm_kernel<<<dim3(HIDN/128, (Bsz*SEQ)/128), 256, gsmem>>>(
        attn_p, wo, out, Bsz*SEQ, HIDN, HIDN);
}

// round 4
// speedup vs baseline: 3.9961x; 1.0023x over previous
#include <cuda_runtime.h>
#include <cuda_bf16.h>
#include <math.h>
#include <stdint.h>

#define Bsz 2
#define SEQ 2048
#define HIDN 2048
#define NH 16
#define NKV 4
#define HD 128
#define QKVF 5120   // (16*2 + 2*4) * 128

// ---------------- scratch (device globals; no allocs allowed) ----------------
__device__ float g_qkv [Bsz*SEQ*QKVF];     // (b*s, 5120)
__device__ float g_q   [Bsz*NH *SEQ*HD];   // (b, h, s, d)
__device__ float g_k   [Bsz*NKV*SEQ*HD];   // (b, kv, s, d)
__device__ float g_v   [Bsz*NKV*SEQ*HD];   // (b, kv, s, d)
__device__ float g_gate[Bsz*SEQ*NH*HD];    // (b*s, h*d) raw gate (pre-sigmoid)
__device__ float g_attn[Bsz*SEQ*NH*HD];    // (b*s, h*d) gated attention output
__device__ float g_rcos[Bsz*SEQ*16];       // rope tables per (row, freq)
__device__ float g_rsin[Bsz*SEQ*16];

// ======================= tf32 helpers =======================================
__device__ __forceinline__ void cp_async16(float* sdst, const float* gsrc) {
    uint32_t s = (uint32_t)__cvta_generic_to_shared(sdst);
    asm volatile("cp.async.cg.shared.global [%0], [%1], 16;\n" :: "r"(s), "l"(gsrc));
}
template<int N_> __device__ __forceinline__ void cp_wait() {
    asm volatile("cp.async.wait_group %0;\n" :: "n"(N_) : "memory");
}
__device__ __forceinline__ uint32_t f2tf32(float x) {
    uint32_t r; asm("cvt.rna.tf32.f32 %0, %1;" : "=r"(r) : "f"(x)); return r;
}
__device__ __forceinline__ void mma8(float* c, const uint32_t* a, const uint32_t* b) {
    asm volatile("mma.sync.aligned.m16n8k8.row.col.f32.tf32.tf32.f32 "
        "{%0,%1,%2,%3}, {%4,%5,%6,%7}, {%8,%9}, {%0,%1,%2,%3};\n"
        : "+f"(c[0]), "+f"(c[1]), "+f"(c[2]), "+f"(c[3])
        : "r"(a[0]), "r"(a[1]), "r"(a[2]), "r"(a[3]), "r"(b[0]), "r"(b[1]));
}

// ======================= tf32 tensor-core GEMM ==============================
// Block tile 128m x 256n x 16k, 8 warps (2m x 4n), warp tile 64x64.
#define KC2 16
#define AP 20          // A smem pitch (20 % 32 == 4 -> conflict-free a-frags)
#define BP 264         // B smem pitch (264 % 32 == 8 -> conflict-free b-frags)
#define ASTG2 (128*AP)
#define BSTG2 (KC2*BP)

__device__ __forceinline__ void gemm_load_stage2(
    float* As, float* Bsm, const float* __restrict__ A, const float* __restrict__ B,
    int tid, int row0, int col0, int k0, int N, int K)
{
#pragma unroll
    for (int t = 0; t < 2; t++) {           // A: 128 x 16 = 512 float4
        int idx = t*256 + tid;
        int r = idx >> 2, c4 = idx & 3;
        cp_async16(As + r*AP + c4*4, A + (size_t)(row0 + r)*K + k0 + c4*4);
    }
#pragma unroll
    for (int t = 0; t < 4; t++) {           // B: 16 x 256 = 1024 float4
        int idx = t*256 + tid;
        int kr = idx >> 6, n4 = idx & 63;
        cp_async16(Bsm + kr*BP + n4*4, B + (size_t)(k0 + kr)*N + col0 + n4*4);
    }
    asm volatile("cp.async.commit_group;\n");
}

__global__ __launch_bounds__(256, 1) void tf32gemm_kernel(
    const float* __restrict__ A, const float* __restrict__ B,
    float* __restrict__ C, int M, int N, int K)
{
    extern __shared__ float smem[];
    float* As  = smem;               // 2 stages 128x20
    float* Bsm = smem + 2*ASTG2;     // 2 stages 16x264

    const int tid = threadIdx.x;
    const int row0 = blockIdx.y * 128, col0 = blockIdx.x * 256;
    const int warp = tid >> 5, lane = tid & 31;
    const int wm = warp >> 2, wn = warp & 3;   // 2m x 4n warps, warp tile 64x64
    const int g = lane >> 2, q = lane & 3;

    float c[4][8][4];
#pragma unroll
    for (int mt = 0; mt < 4; mt++)
#pragma unroll
        for (int nt = 0; nt < 8; nt++)
#pragma unroll
            for (int i = 0; i < 4; i++) c[mt][nt][i] = 0.f;

    const int T = K / KC2;
    gemm_load_stage2(As, Bsm, A, B, tid, row0, col0, 0, N, K);

    for (int it = 0; it < T; it++) {
        if (it + 1 < T) {
            gemm_load_stage2(As + ((it+1)&1)*ASTG2, Bsm + ((it+1)&1)*BSTG2,
                             A, B, tid, row0, col0, (it+1)*KC2, N, K);
            cp_wait<1>();
        } else {
            cp_wait<0>();
        }
        __syncthreads();

        const float* As_ = As  + (it&1)*ASTG2;
        const float* Bs_ = Bsm + (it&1)*BSTG2;
#pragma unroll
        for (int kk = 0; kk < KC2; kk += 8) {
            uint32_t af[4][4], bf[8][2];
#pragma unroll
            for (int mt = 0; mt < 4; mt++) {
                const float* p = As_ + (wm*64 + mt*16 + g)*AP + kk + q;
                af[mt][0] = f2tf32(p[0]);
                af[mt][2] = f2tf32(p[4]);
                af[mt][1] = f2tf32(p[8*AP]);
                af[mt][3] = f2tf32(p[8*AP + 4]);
            }
#pragma unroll
            for (int nt = 0; nt < 8; nt++) {
                int cc = wn*64 + nt*8 + g;
                bf[nt][0] = f2tf32(Bs_[(kk + q)*BP + cc]);
                bf[nt][1] = f2tf32(Bs_[(kk + q + 4)*BP + cc]);
            }
#pragma unroll
            for (int mt = 0; mt < 4; mt++)
#pragma unroll
                for (int nt = 0; nt < 8; nt++)
                    mma8(c[mt][nt], af[mt], bf[nt]);
        }
        __syncthreads();
    }

#pragma unroll
    for (int mt = 0; mt < 4; mt++) {
        int r_ = row0 + wm*64 + mt*16 + g;
#pragma unroll
        for (int nt = 0; nt < 8; nt++) {
            int cc = col0 + wn*64 + nt*8 + q*2;
            *(float2*)(C + (size_t)r_*N + cc)     = make_float2(c[mt][nt][0], c[mt][nt][1]);
            *(float2*)(C + (size_t)(r_+8)*N + cc) = make_float2(c[mt][nt][2], c[mt][nt][3]);
        }
    }
}

// ---------------- rope table (fp64 trig once per (row,freq)) -----------------
__global__ __launch_bounds__(256) void rope_table_kernel(const int* __restrict__ positions)
{
    int i = blockIdx.x * 256 + threadIdx.x;   // < 4096*16
    int row = i >> 4, fi = i & 15;
    int pos = positions[row];
    double invf = exp(-(double)fi * (1.0/16.0) * log(5.0e6));
    float ang = (float)pos * (float)invf;
    double sd, cd;
    sincos((double)ang, &sd, &cd);
    g_rcos[i] = (float)cd;
    g_rsin[i] = (float)sd;
}

// ---------------- RMSNorm + partial RoPE + scatter to q/k/v/gate -------------
__global__ __launch_bounds__(256) void postqkv_kernel(
    const float* __restrict__ qw, const float* __restrict__ kw)
{
    int row = blockIdx.x;                 // b*SEQ + s
    int b = row / SEQ, s = row % SEQ;
    int lane = threadIdx.x & 31, warp = threadIdx.x >> 5;
    const float* qrow = g_qkv + (size_t)row * QKVF;

    for (int vi = warp; vi < NH + NKV; vi += 8) {
        const float* src; float* dst; const float* w;
        if (vi < NH) {
            src = qrow + vi * 256;
            dst = g_q + (((size_t)b*NH + vi)*SEQ + s)*HD;
            w = qw;
        } else {
            int kv = vi - NH;
            src = qrow + NH*2*HD + kv*HD;
            dst = g_k + (((size_t)b*NKV + kv)*SEQ + s)*HD;
            w = kw;
        }
        float x0 = src[lane], x1 = src[lane+32], x2 = src[lane+64], x3 = src[lane+96];
        float ss = x0*x0 + x1*x1 + x2*x2 + x3*x3;
#pragma unroll
        for (int o = 16; o > 0; o >>= 1) ss += __shfl_xor_sync(0xffffffffu, ss, o);
        float inv = rsqrtf(ss * (1.0f/128.0f) + 1e-6f);
        x0 *= inv * (1.f + w[lane]);
        x1 *= inv * (1.f + w[lane+32]);
        x2 *= inv * (1.f + w[lane+64]);
        x3 *= inv * (1.f + w[lane+96]);
        int fi = lane & 15;
        float partner = __shfl_xor_sync(0xffffffffu, x0, 16);
        float cf = g_rcos[row*16 + fi], sf = g_rsin[row*16 + fi];
        float y0 = (lane < 16) ? (x0*cf - partner*sf) : (x0*cf + partner*sf);
        dst[lane]    = y0;
        dst[lane+32] = x1;
        dst[lane+64] = x2;
        dst[lane+96] = x3;
    }
    for (int i = threadIdx.x; i < NH*HD; i += blockDim.x) {
        int h = i >> 7, d = i & 127;
        g_gate[(size_t)row*NH*HD + i] = qrow[h*256 + 128 + d];
    }
    for (int i = threadIdx.x; i < NKV*HD; i += blockDim.x) {
        int kv = i >> 7, d = i & 127;
        g_v[(((size_t)b*NKV + kv)*SEQ + s)*HD + d] = qrow[NH*2*HD + NKV*HD + i];
    }
}

// ---------------- tensor-core causal flash attention + gating ----------------
// BM=128 q-rows per CTA (8 warps x m16), BN=64 kv-rows per tile.
// K and V both stored s-major (no transpose); V frags read with row-stride.
#define KP 132    // 132 % 32 == 4: K b-frags (n-outer) conflict-free
#define VP 136    // 136 % 32 == 8: V b-frags (k-outer) conflict-free
#define PP 68     // 68 % 32 == 4: P a-frags conflict-free
#define AT_WORDS (64*KP + 64*VP + 128*PP)   // 8448 + 8704 + 8704 = 25856

__global__ __launch_bounds__(256, 1) void attn_mma_kernel()
{
    extern __shared__ uint32_t smu[];
    uint32_t* Ks = smu;              // 64 x 132 (s-major, tf32 bits)
    uint32_t* Vs = smu + 64*KP;      // 64 x 136 (s-major, tf32 bits)
    uint32_t* Ps = Vs + 64*VP;       // 128 x 68 (tf32 bits)

    const int tid = threadIdx.x, lane = tid & 31, warp = tid >> 5;
    const int g = lane >> 2, q = lane & 3;
    const int hh = blockIdx.y;
    const int b = hh >> 4, h = hh & 15, kvh = h >> 2;
    const int m_tile = gridDim.x - 1 - blockIdx.x;   // heavy tiles first
    const int m0 = m_tile * 128;

    const float* Qg = g_q + (((size_t)b*NH + h)*SEQ + m0)*HD;
    const float* Kg = g_k + ((size_t)b*NKV + kvh)*SEQ*HD;
    const float* Vg = g_v + ((size_t)b*NKV + kvh)*SEQ*HD;

    // Q fragments in registers, pre-scaled by 1/sqrt(D); warp owns rows warp*16..+15
    const float scale = 0.08838834764831845f;
    uint32_t aq[16][4];
    {
        const float* q0 = Qg + (size_t)(warp*16 + g)*HD;
        const float* q1 = q0 + 8*HD;
#pragma unroll
        for (int ks = 0; ks < 16; ks++) {
            aq[ks][0] = f2tf32(q0[ks*8 + q]     * scale);
            aq[ks][1] = f2tf32(q1[ks*8 + q]     * scale);
            aq[ks][2] = f2tf32(q0[ks*8 + q + 4] * scale);
            aq[ks][3] = f2tf32(q1[ks*8 + q + 4] * scale);
        }
    }

    float o[16][4];
#pragma unroll
    for (int nt = 0; nt < 16; nt++)
#pragma unroll
        for (int i = 0; i < 4; i++) o[nt][i] = 0.f;
    float rm0 = -3.0e38f, rm1 = -3.0e38f, rl0 = 0.f, rl1 = 0.f;

    const int ntiles = 2*m_tile + 2;
    for (int kt = 0; kt < ntiles; kt++) {
        const int n0 = kt * 64;
        __syncthreads();   // previous tile's reads done before overwrite

        // K,V tiles: 64 x 128 each, float4 LDG + cvt + float4 STS
#pragma unroll
        for (int t = 0; t < 8; t++) {
            int idx = t*256 + tid;
            int r = idx >> 5, c4 = idx & 31;
            float4 k4 = *(const float4*)(Kg + (size_t)(n0 + r)*HD + c4*4);
            *(uint4*)(Ks + r*KP + c4*4) =
                make_uint4(f2tf32(k4.x), f2tf32(k4.y), f2tf32(k4.z), f2tf32(k4.w));
        }
#pragma unroll
        for (int t = 0; t < 8; t++) {
            int idx = t*256 + tid;
            int r = idx >> 5, c4 = idx & 31;
            float4 v4 = *(const float4*)(Vg + (size_t)(n0 + r)*HD + c4*4);
            *(uint4*)(Vs + r*VP + c4*4) =
                make_uint4(f2tf32(v4.x), f2tf32(v4.y), f2tf32(v4.z), f2tf32(v4.w));
        }
        __syncthreads();

        // S = Q K^T (warp rows warp*16..+15, cols 0..63)
        float sc[8][4];
#pragma unroll
        for (int nt = 0; nt < 8; nt++)
#pragma unroll
            for (int i = 0; i < 4; i++) sc[nt][i] = 0.f;
#pragma unroll
        for (int kk = 0; kk < 16; kk++) {
            uint32_t bf[8][2];
#pragma unroll
            for (int nt = 0; nt < 8; nt++) {
                const uint32_t* kp = Ks + (nt*8 + g)*KP + kk*8 + q;
                bf[nt][0] = kp[0];
                bf[nt][1] = kp[4];
            }
#pragma unroll
            for (int nt = 0; nt < 8; nt++)
                mma8(sc[nt], aq[kk], bf[nt]);
        }

        // causal mask on the two diagonal-straddling tiles
        if (kt >= ntiles - 2) {
            int gr0 = m0 + warp*16 + g;
#pragma unroll
            for (int nt = 0; nt < 8; nt++) {
                int gc = n0 + nt*8 + 2*q;
                if (gc     > gr0)     sc[nt][0] = -3.0e38f;
                if (gc + 1 > gr0)     sc[nt][1] = -3.0e38f;
                if (gc     > gr0 + 8) sc[nt][2] = -3.0e38f;
                if (gc + 1 > gr0 + 8) sc[nt][3] = -3.0e38f;
            }
        }

        // online softmax (rows g and g+8 of this warp's m16 block)
        float mx0 = -3.0e38f, mx1 = -3.0e38f;
#pragma unroll
        for (int nt = 0; nt < 8; nt++) {
            mx0 = fmaxf(mx0, fmaxf(sc[nt][0], sc[nt][1]));
            mx1 = fmaxf(mx1, fmaxf(sc[nt][2], sc[nt][3]));
        }
        mx0 = fmaxf(mx0, __shfl_xor_sync(0xffffffffu, mx0, 1));
        mx0 = fmaxf(mx0, __shfl_xor_sync(0xffffffffu, mx0, 2));
        mx1 = fmaxf(mx1, __shfl_xor_sync(0xffffffffu, mx1, 1));
        mx1 = fmaxf(mx1, __shfl_xor_sync(0xffffffffu, mx1, 2));
        float nm0 = fmaxf(rm0, mx0), nm1 = fmaxf(rm1, mx1);
        float corr0 = __expf(rm0 - nm0), corr1 = __expf(rm1 - nm1);
        float sum0 = 0.f, sum1 = 0.f;
#pragma unroll
        for (int nt = 0; nt < 8; nt++) {
            sc[nt][0] = __expf(sc[nt][0] - nm0); sum0 += sc[nt][0];
            sc[nt][1] = __expf(sc[nt][1] - nm0); sum0 += sc[nt][1];
            sc[nt][2] = __expf(sc[nt][2] - nm1); sum1 += sc[nt][2];
            sc[nt][3] = __expf(sc[nt][3] - nm1); sum1 += sc[nt][3];
        }
        sum0 += __shfl_xor_sync(0xffffffffu, sum0, 1);
        sum0 += __shfl_xor_sync(0xffffffffu, sum0, 2);
        sum1 += __shfl_xor_sync(0xffffffffu, sum1, 1);
        sum1 += __shfl_xor_sync(0xffffffffu, sum1, 2);
        rl0 = rl0 * corr0 + sum0;  rl1 = rl1 * corr1 + sum1;
        rm0 = nm0;  rm1 = nm1;

        // store P (tf32 bits) into warp-private Ps rows
        {
            uint32_t* p0 = Ps + (warp*16 + g)*PP;
            uint32_t* p1 = p0 + 8*PP;
#pragma unroll
            for (int nt = 0; nt < 8; nt++) {
                int cc = nt*8 + 2*q;
                *(uint2*)(p0 + cc) = make_uint2(f2tf32(sc[nt][0]), f2tf32(sc[nt][1]));
                *(uint2*)(p1 + cc) = make_uint2(f2tf32(sc[nt][2]), f2tf32(sc[nt][3]));
            }
        }
        __syncwarp();

        // rescale O, then O += P @ V  (V read s-major with row stride)
#pragma unroll
        for (int nt = 0; nt < 16; nt++) {
            o[nt][0] *= corr0; o[nt][1] *= corr0;
            o[nt][2] *= corr1; o[nt][3] *= corr1;
        }
#pragma unroll
        for (int kk = 0; kk < 8; kk++) {
            uint32_t ap[4];
            const uint32_t* pp = Ps + (warp*16 + g)*PP + kk*8 + q;
            ap[0] = pp[0];
            ap[2] = pp[4];
            ap[1] = pp[8*PP];
            ap[3] = pp[8*PP + 4];
#pragma unroll
            for (int nt = 0; nt < 16; nt++) {
                const uint32_t* vp = Vs + (kk*8 + q)*VP + nt*8 + g;
                uint32_t bv[2] = { vp[0], vp[4*VP] };
                mma8(o[nt], ap, bv);
            }
        }
    }

    // epilogue: normalize, sigmoid-gate, write to (b*s, h*d)
    float linv0 = 1.0f / rl0, linv1 = 1.0f / rl1;
    int r0 = m0 + warp*16 + g;
#pragma unroll
    for (int nt = 0; nt < 16; nt++) {
        int d = nt*8 + 2*q;
        size_t base0 = ((size_t)b*SEQ + r0)*(NH*HD) + h*HD + d;
        size_t base1 = base0 + 8*(size_t)(NH*HD);
        float g00 = g_gate[base0], g01 = g_gate[base0+1];
        float g10 = g_gate[base1], g11 = g_gate[base1+1];
        float2 o0 = make_float2(o[nt][0]*linv0 / (1.f + __expf(-g00)),
                                o[nt][1]*linv0 / (1.f + __expf(-g01)));
        float2 o1 = make_float2(o[nt][2]*linv1 / (1.f + __expf(-g10)),
                                o[nt][3]*linv1 / (1.f + __expf(-g11)));
        *(float2*)(g_attn + base0) = o0;
        *(float2*)(g_attn + base1) = o1;
    }
}

// ---------------- host launch ------------------------------------------------
extern "C" void kernel_launch(void* const* d_in, const int* in_sizes, int n_in,
                              void* d_out, int out_size)
{
    const float* x         = (const float*)d_in[0];
    const int*   positions = (const int*)  d_in[1];
    /* d_in[2] = attention_mask: all-ones; causal mask dominates -> unused */
    const float* wqkv      = (const float*)d_in[3];
    const float* wo        = (const float*)d_in[4];
    const float* qw        = (const float*)d_in[5];
    const float* kw        = (const float*)d_in[6];
    float* out = (float*)d_out;

    float *qkv_p, *attn_p;
    cudaGetSymbolAddress((void**)&qkv_p,  g_qkv);
    cudaGetSymbolAddress((void**)&attn_p, g_attn);

    int gsmem = 2*(ASTG2 + BSTG2) * (int)sizeof(float);   // 54,272 B
    cudaFuncSetAttribute(tf32gemm_kernel, cudaFuncAttributeMaxDynamicSharedMemorySize, gsmem);

    // 1) QKV projection: (4096 x 2048) @ (2048 x 5120)
    tf32gemm_kernel<<<dim3(QKVF/256, (Bsz*SEQ)/128), 256, gsmem>>>(
        x, wqkv, qkv_p, Bsz*SEQ, QKVF, HIDN);

    // 2) rope table + norm/rope/scatter
    rope_table_kernel<<<(Bsz*SEQ*16)/256, 256>>>(positions);
    postqkv_kernel<<<Bsz*SEQ, 256>>>(qw, kw);

    // 3) tensor-core causal flash attention + gating
    int asmem = AT_WORDS * (int)sizeof(uint32_t);   // 103,424 B
    cudaFuncSetAttribute(attn_mma_kernel, cudaFuncAttributeMaxDynamicSharedMemorySize, asmem);
    attn_mma_kernel<<<dim3(SEQ/128, Bsz*NH), 256, asmem>>>();

    // 4) output projection: (4096 x 2048) @ (2048 x 2048)
    tf32gemm_kernel<<<dim3(HIDN/256, (Bsz*SEQ)/128), 256, gsmem>>>(
        attn_p, wo, out, Bsz*SEQ, HIDN, HIDN);
}